// round 10
// baseline (speedup 1.0000x reference)
#include <cuda_runtime.h>
#include <cuda_bf16.h>
#include <cstdint>

// LogSignature depth=4 of path (B=128, T=512, C=8).
// Output per batch: [L1(8) | L2(64) | L3(512) | L4(4096)] = 4680 floats.
//
// ROUND 10: (i,j)-ownership scan. One CTA per batch, 512 threads =
// 64 (i,j) pairs x 8 time segments (64 steps each, scalar fp32).
// Per thread/step: shared factors n_g, n2 once, then
//   g[k]  = r3[k] + n_g*d[k];  r3[k] += n2*d[k]     (16 FMA)
//   a[k][l] += g[k]*d[l]                            (64 FMA)
//   r2 += r1*dj + 0.5*di*dj;  r1 += di              (3)
// = 90 FMA per 8 ijk-rows vs 168 in the (i,j,k)-per-thread layout.
// Segments are Chen-combined with a 3-round shfl-xor tree (L4 in regs,
// levels<=3 via smem), then closed-form truncated log.

#define BATCH 128
#define TLEN  512
#define CH    8
#define NSTEP (TLEN - 1)     // 511
#define NSEG  8
#define SEGLEN 64            // steps per segment (seg 7: 63 real + 1 zero pad)
#define OUT_STRIDE 4680
#define OFF_L2 8
#define OFF_L3 72
#define OFF_L4 584

#define C3F (1.0f / 6.0f)
#define C4F (1.0f / 24.0f)

__global__ void __launch_bounds__(512, 1)
logsig_kernel(const float* __restrict__ path, float* __restrict__ out)
{
    __shared__ __align__(16) float s_dx[TLEN * CH];   // 16 KB; slot 511 zeroed
    __shared__ __align__(16) float sL[NSEG][584];     // per-group levels 1..3

    const int b   = blockIdx.x;
    const int tid = threadIdx.x;
    const float* p = path + (size_t)b * TLEN * CH;

    // increments (slot NSTEP..TLEN-1 = 0 -> exp(0) = identity pad)
    for (int idx = tid; idx < TLEN * CH; idx += 512) {
        float v = 0.0f;
        if (idx < NSTEP * CH) v = p[idx + CH] - p[idx];
        s_dx[idx] = v;
    }
    __syncthreads();

    const int ij = tid >> 3;          // 0..63
    const int i  = ij >> 3;
    const int j  = ij & 7;
    const int s  = tid & 7;           // segment = lane bits 0..2

    float a[8][8];
    float r3[8];
    float r1 = 0.0f, r2 = 0.0f;
    #pragma unroll
    for (int k = 0; k < 8; ++k) {
        r3[k] = 0.0f;
        #pragma unroll
        for (int l = 0; l < 8; ++l) a[k][l] = 0.0f;
    }

    // ---- scan own segment ----
    {
        const float* d = &s_dx[s * SEGLEN * CH];
        #pragma unroll 1
        for (int t = 0; t < SEGLEN; ++t, d += CH) {
            const float4 dlo = *(const float4*)(d);
            const float4 dhi = *(const float4*)(d + 4);
            const float dv[8] = {dlo.x, dlo.y, dlo.z, dlo.w,
                                 dhi.x, dhi.y, dhi.z, dhi.w};
            const float di = d[i];            // scalar LDS (runtime i)
            const float dj = d[j];

            const float didj = di * dj;
            const float r1dj = r1 * dj;

            float ng = 0.5f * r2;             // n_g = c2 r2 + c3 r1dj + c4 didj
            ng = fmaf(C3F, r1dj, ng);
            ng = fmaf(C4F, didj, ng);
            float n2 = fmaf(0.5f, r1dj, r2);  // n2 = r2 + c2 r1dj + c3 didj
            n2 = fmaf(C3F, didj, n2);

            float g[8];
            #pragma unroll
            for (int k = 0; k < 8; ++k) {
                g[k]  = fmaf(ng, dv[k], r3[k]);   // old r3
                r3[k] = fmaf(n2, dv[k], r3[k]);
            }
            #pragma unroll
            for (int k = 0; k < 8; ++k)
                #pragma unroll
                for (int l = 0; l < 8; ++l)
                    a[k][l] = fmaf(g[k], dv[l], a[k][l]);

            r2 = fmaf(0.5f, didj, r1dj) + r2;
            r1 += di;
        }
    }

    // ---- publish own segment levels 1..3 ----
    auto publish = [&](void) {
        #pragma unroll
        for (int k = 0; k < 8; ++k) sL[s][72 + ij * 8 + k] = r3[k];
        sL[s][8 + ij] = r2;
        if (j == 0) sL[s][i] = r1;
    };
    publish();
    __syncthreads();

    // ---- 3-round Chen combine tree over segments ----
    #pragma unroll 1
    for (int r = 0; r < 3; ++r) {
        const int blk   = 1 << r;
        const int Abase = s & ~((blk << 1) - 1);
        const int Bbase = Abase + blk;
        const float* LA = sL[Abase];
        const float* LB = sL[Bbase];

        const float A1 = LA[i];
        const float A2 = LA[8 + ij];
        float A3k[8];
        #pragma unroll
        for (int k = 0; k < 8; ++k) A3k[k] = LA[72 + ij * 8 + k];

        const float B1i = LB[i];
        const float B1j = LB[j];
        const float B2ij = LB[8 + ij];

        // combined levels 1..3
        const float c1 = A1 + B1i;
        const float c2v = A2 + B2ij + A1 * B1j;
        float c3[8];
        #pragma unroll
        for (int k = 0; k < 8; ++k) {
            float t = A3k[k] + LB[72 + ij * 8 + k];
            t = fmaf(A1, LB[8 + j * 8 + k], t);
            t = fmaf(A2, LB[k], t);
            c3[k] = t;
        }

        // combined L4: own + partner (shfl) + cross terms
        #pragma unroll
        for (int k = 0; k < 8; ++k) {
            const float4 b3lo = *(const float4*)(&LB[72 + (j * 8 + k) * 8]);
            const float4 b3hi = *(const float4*)(&LB[72 + (j * 8 + k) * 8 + 4]);
            const float4 b2lo = *(const float4*)(&LB[8 + k * 8]);
            const float4 b2hi = *(const float4*)(&LB[8 + k * 8 + 4]);
            const float b3r[8] = {b3lo.x, b3lo.y, b3lo.z, b3lo.w,
                                  b3hi.x, b3hi.y, b3hi.z, b3hi.w};
            const float b2r[8] = {b2lo.x, b2lo.y, b2lo.z, b2lo.w,
                                  b2hi.x, b2hi.y, b2hi.z, b2hi.w};
            #pragma unroll
            for (int l = 0; l < 8; ++l) {
                float t = a[k][l] + __shfl_xor_sync(0xffffffffu, a[k][l], blk);
                t = fmaf(A1, b3r[l], t);
                t = fmaf(A2, b2r[l], t);
                t = fmaf(A3k[k], LB[l], t);
                a[k][l] = t;
            }
        }

        r1 = c1;
        r2 = c2v;
        #pragma unroll
        for (int k = 0; k < 8; ++k) r3[k] = c3[k];

        __syncthreads();     // all reads of sL done
        publish();
        __syncthreads();
    }

    // ---- closed-form log(1+x) truncated at depth 4 ----
    // final combined levels are in sL[0] (all slots identical)
    const float* L = sL[0];
    const float4 v1lo = *(const float4*)(&L[0]);
    const float4 v1hi = *(const float4*)(&L[4]);
    const float v1[8] = {v1lo.x, v1lo.y, v1lo.z, v1lo.w,
                         v1hi.x, v1hi.y, v1hi.z, v1hi.w};
    const float si = v1[i];
    const float sj = v1[j];
    const float sisj = si * sj;
    const float Q = fmaf(1.0f / 3.0f, sisj, -0.5f * r2);   // per-(i,j)
    const float R = -0.5f * si;

    float* ob = out + (size_t)b * OUT_STRIDE;

    float o4[8][8];
    float o3[8];
    #pragma unroll
    for (int k = 0; k < 8; ++k) {
        const float sk = v1[k];
        const float s2jk = L[8 + j * 8 + k];
        const float cross = fmaf(si, s2jk, r2 * sk);        // si*s2jk + s2ij*sk
        const float sss = sisj * sk;
        const float P = fmaf(1.0f / 3.0f, cross, -0.5f * r3[k]) - 0.25f * sss;
        o3[k] = fmaf(1.0f / 3.0f, sss, fmaf(-0.5f, cross, r3[k]));

        const float4 b3lo = *(const float4*)(&L[72 + (j * 8 + k) * 8]);
        const float4 b3hi = *(const float4*)(&L[72 + (j * 8 + k) * 8 + 4]);
        const float4 b2lo = *(const float4*)(&L[8 + k * 8]);
        const float4 b2hi = *(const float4*)(&L[8 + k * 8 + 4]);
        const float s3r[8] = {b3lo.x, b3lo.y, b3lo.z, b3lo.w,
                              b3hi.x, b3hi.y, b3hi.z, b3hi.w};
        const float s2r[8] = {b2lo.x, b2lo.y, b2lo.z, b2lo.w,
                              b2hi.x, b2hi.y, b2hi.z, b2hi.w};
        #pragma unroll
        for (int l = 0; l < 8; ++l) {
            float t = fmaf(P, v1[l], a[k][l]);
            t = fmaf(Q, s2r[l], t);
            t = fmaf(R, s3r[l], t);
            o4[k][l] = t;
        }
    }

    // ---- stores: thread (ij, s) writes k == s row (all s hold identical data) ----
    #pragma unroll
    for (int k = 0; k < 8; ++k) {
        if (k == s) {
            float4 w0 = {o4[k][0], o4[k][1], o4[k][2], o4[k][3]};
            float4 w1 = {o4[k][4], o4[k][5], o4[k][6], o4[k][7]};
            *(float4*)(&ob[OFF_L4 + (ij * 8 + k) * 8])     = w0;
            *(float4*)(&ob[OFF_L4 + (ij * 8 + k) * 8 + 4]) = w1;
            ob[OFF_L3 + ij * 8 + k] = o3[k];
        }
    }
    if (s == 0)
        ob[OFF_L2 + ij] = fmaf(-0.5f, sisj, r2);
    if (s == 0 && j == 0)
        ob[i] = r1;
}

extern "C" void kernel_launch(void* const* d_in, const int* in_sizes, int n_in,
                              void* d_out, int out_size)
{
    const float* path = (const float*)d_in[0];
    float* out = (float*)d_out;
    logsig_kernel<<<BATCH, 512>>>(path, out);
}